// round 2
// baseline (speedup 1.0000x reference)
#include <cuda_runtime.h>
#include <cuda_bf16.h>

#define NSP 8192
#define NR  2097152
#define NG  (NR / 4)   // vec4 reaction groups

// metadata order:
// 0 abundances[8192] f32, 1 temperature, 2 cr_rate, 3 fuv_rate,
// 4 alpha[NR], 5 beta[NR], 6 gamma[NR], 7 rtype[NR] i32,
// 8 react_species[NR,2] i32, 9 inc_rows[4*NR] i32,
// 10 inc_cols (structurally repeat(arange(NR),4) -- unused),
// 11 inc_vals (structurally -1,-1,+1,+1 per reaction -- unused), 12 n_species

__device__ __forceinline__ float ex2_approx(float x) {
    float y;
    asm("ex2.approx.ftz.f32 %0, %1;" : "=f"(y) : "f"(x));
    return y;
}

__global__ void zero_out_kernel(float* __restrict__ out, int n) {
    int i = blockIdx.x * blockDim.x + threadIdx.x;
    if (i < n) out[i] = 0.0f;
}

__global__ __launch_bounds__(1024, 2)
void rates_scatter_kernel(
    const float*  __restrict__ abund,
    const float*  __restrict__ Tptr,
    const float*  __restrict__ crptr,
    const float*  __restrict__ fuvptr,
    const float4* __restrict__ alpha4,
    const float4* __restrict__ beta4,
    const float4* __restrict__ gamma4,
    const int4*   __restrict__ rtype4,
    const int4*   __restrict__ rspec2,  // [NR/2] : two reactions' (s0,s1) pairs
    const int4*   __restrict__ rows4,   // [NR]   : one reaction's 4 incidence rows
    float* __restrict__ out)
{
    __shared__ float acc[NSP];
    for (int i = threadIdx.x; i < NSP; i += blockDim.x) acc[i] = 0.0f;
    __syncthreads();

    const float T   = *Tptr;
    const float cr  = *crptr;
    const float fuv = *fuvptr;
    const float L2E = 1.4426950408889634f;           // log2(e)
    const float c1  = __log2f(T * (1.0f / 300.0f));  // log2(T/300)
    const float c2  = -L2E / T;                      // exp(-g/T) = exp2(g*c2)

    const int stride = gridDim.x * blockDim.x;
    for (int g = blockIdx.x * blockDim.x + threadIdx.x; g < NG; g += stride) {
        // Front-batched wide loads: 10 independent LDG.128 per group of 4 reactions.
        const float4 a4 = alpha4[g];
        const float4 b4 = beta4[g];
        const float4 g4 = gamma4[g];
        const int4   t4 = rtype4[g];
        const int4   s0 = rspec2[2 * g];      // reactions 4g, 4g+1
        const int4   s1 = rspec2[2 * g + 1];  // reactions 4g+2, 4g+3
        const int4   r0 = rows4[4 * g];
        const int4   r1 = rows4[4 * g + 1];
        const int4   r2 = rows4[4 * g + 2];
        const int4   r3 = rows4[4 * g + 3];

        const float a[4] = {a4.x, a4.y, a4.z, a4.w};
        const float b[4] = {b4.x, b4.y, b4.z, b4.w};
        const float gm[4] = {g4.x, g4.y, g4.z, g4.w};
        const int   t[4] = {t4.x, t4.y, t4.z, t4.w};
        const int   sx[4] = {s0.x, s0.z, s1.x, s1.z};
        const int   sy[4] = {s0.y, s0.w, s1.y, s1.w};
        const int4  rw[4] = {r0, r1, r2, r3};

        #pragma unroll
        for (int j = 0; j < 4; j++) {
            // One exp2 serves type-0 (b*c1 + g*c2) and type-2 (-g*log2e).
            const float e  = (t[j] == 0) ? fmaf(b[j], c1, gm[j] * c2)
                                         : (-gm[j] * L2E);
            const float ex = ex2_approx(e);
            float k;
            if (t[j] == 1)      k = a[j] * cr;
            else if (t[j] == 2) k = a[j] * fuv * ex;
            else                k = a[j] * ex;

            k *= __ldg(&abund[sx[j]]) * __ldg(&abund[sy[j]]);

            atomicAdd(&acc[rw[j].x], -k);
            atomicAdd(&acc[rw[j].y], -k);
            atomicAdd(&acc[rw[j].z],  k);
            atomicAdd(&acc[rw[j].w],  k);
        }
    }

    __syncthreads();
    for (int i = threadIdx.x; i < NSP; i += blockDim.x)
        atomicAdd(&out[i], acc[i]);   // result unused -> REDG
}

extern "C" void kernel_launch(void* const* d_in, const int* in_sizes, int n_in,
                              void* d_out, int out_size) {
    const float* abund  = (const float*)d_in[0];
    const float* T      = (const float*)d_in[1];
    const float* crr    = (const float*)d_in[2];
    const float* fuvr   = (const float*)d_in[3];
    float* out = (float*)d_out;

    zero_out_kernel<<<(out_size + 255) / 256, 256>>>(out, out_size);

    rates_scatter_kernel<<<296, 1024>>>(
        abund, T, crr, fuvr,
        (const float4*)d_in[4], (const float4*)d_in[5], (const float4*)d_in[6],
        (const int4*)d_in[7], (const int4*)d_in[8], (const int4*)d_in[9],
        out);
}

// round 3
// speedup vs baseline: 1.3661x; 1.3661x over previous
#include <cuda_runtime.h>
#include <cuda_bf16.h>

#define NSP 8192
#define NR  2097152

// metadata order:
// 0 abundances[8192] f32, 1 temperature, 2 cr_rate, 3 fuv_rate,
// 4 alpha[NR], 5 beta[NR], 6 gamma[NR], 7 rtype[NR] i32,
// 8 react_species[NR,2] i32, 9 inc_rows[4*NR] i32,
// 10 inc_cols (structurally repeat(arange(NR),4) -- unused),
// 11 inc_vals (structurally -1,-1,+1,+1 per reaction -- unused), 12 n_species

__device__ __forceinline__ float ex2_approx(float x) {
    float y;
    asm("ex2.approx.ftz.f32 %0, %1;" : "=f"(y) : "f"(x));
    return y;
}

__global__ void zero_out_kernel(float* __restrict__ out, int n) {
    int i = blockIdx.x * blockDim.x + threadIdx.x;
    if (i < n) out[i] = 0.0f;
}

__global__ __launch_bounds__(1024, 2)
void rates_scatter_kernel(
    const float* __restrict__ abund,
    const float* __restrict__ Tptr,
    const float* __restrict__ crptr,
    const float* __restrict__ fuvptr,
    const float* __restrict__ alpha,
    const float* __restrict__ beta,
    const float* __restrict__ gamma,
    const int*   __restrict__ rtype,
    const int2*  __restrict__ rspec,   // [NR] reactant pairs
    const int4*  __restrict__ rows4,   // [NR] incidence-row quads
    float* __restrict__ out)
{
    extern __shared__ float smem[];
    float* acc = smem;          // [NSP] per-CTA accumulator
    float* sab = smem + NSP;    // [NSP] staged abundances (LDS gather, not L1tex)

    for (int i = threadIdx.x; i < NSP; i += blockDim.x) {
        acc[i] = 0.0f;
        sab[i] = abund[i];
    }
    __syncthreads();

    const float T   = *Tptr;
    const float cr  = *crptr;
    const float fuv = *fuvptr;
    const float L2E = 1.4426950408889634f;           // log2(e)
    const float c1  = __log2f(T * (1.0f / 300.0f));  // log2(T/300)
    const float c2  = -L2E / T;                      // exp(-g/T) = exp2(g*c2)

    const int stride = gridDim.x * blockDim.x;
    for (int r = blockIdx.x * blockDim.x + threadIdx.x; r < NR; r += stride) {
        const float a = alpha[r];
        const float b = beta[r];
        const float g = gamma[r];
        const int   t = rtype[r];
        const int2  sp = rspec[r];
        const int4  rw = rows4[r];

        // Single exp2 serves type-0 (b*c1 + g*c2) and type-2 (-g*log2e).
        const float e  = (t == 0) ? fmaf(b, c1, g * c2) : (-g * L2E);
        const float ex = ex2_approx(e);
        float k;
        if (t == 1)      k = a * cr;
        else if (t == 2) k = a * fuv * ex;
        else             k = a * ex;

        k *= sab[sp.x] * sab[sp.y];   // LDS gathers (smem crossbar, ~4 cyc)

        atomicAdd(&acc[rw.x], -k);
        atomicAdd(&acc[rw.y], -k);
        atomicAdd(&acc[rw.z],  k);
        atomicAdd(&acc[rw.w],  k);
    }

    __syncthreads();
    for (int i = threadIdx.x; i < NSP; i += blockDim.x)
        atomicAdd(&out[i], acc[i]);   // no-return -> REDG
}

extern "C" void kernel_launch(void* const* d_in, const int* in_sizes, int n_in,
                              void* d_out, int out_size) {
    const float* abund  = (const float*)d_in[0];
    const float* T      = (const float*)d_in[1];
    const float* crr    = (const float*)d_in[2];
    const float* fuvr   = (const float*)d_in[3];
    float* out = (float*)d_out;

    const int smem_bytes = 2 * NSP * sizeof(float);  // 64 KB
    cudaFuncSetAttribute(rates_scatter_kernel,
                         cudaFuncAttributeMaxDynamicSharedMemorySize, smem_bytes);

    zero_out_kernel<<<(out_size + 255) / 256, 256>>>(out, out_size);

    rates_scatter_kernel<<<296, 1024, smem_bytes>>>(
        abund, T, crr, fuvr,
        (const float*)d_in[4], (const float*)d_in[5], (const float*)d_in[6],
        (const int*)d_in[7], (const int2*)d_in[8], (const int4*)d_in[9],
        out);
}